// round 4
// baseline (speedup 1.0000x reference)
#include <cuda_runtime.h>
#include <math.h>

// out_b[k] = p(x_b) . S[k] + beta * x_b[k] + v0[k]
// p(x) = (x0^2, x1^2, x2^2, x0x1, x0x2, x1x2)
// smem const layout: c[0..17]=S (row k = c[6k..6k+5]), c[18]=beta, c[19..21]=v0

__device__ __forceinline__ void eval3(const float* __restrict__ c,
                                      float x0, float x1, float x2,
                                      float& o0, float& o1, float& o2)
{
    float p0 = x0 * x0, p1 = x1 * x1, p2 = x2 * x2;
    float p3 = x0 * x1, p4 = x0 * x2, p5 = x1 * x2;
    float beta = c[18];
    o0 = fmaf(c[0],  p0, fmaf(c[1],  p1, fmaf(c[2],  p2, fmaf(c[3],  p3, fmaf(c[4],  p4, fmaf(c[5],  p5, fmaf(beta, x0, c[19])))))));
    o1 = fmaf(c[6],  p0, fmaf(c[7],  p1, fmaf(c[8],  p2, fmaf(c[9],  p3, fmaf(c[10], p4, fmaf(c[11], p5, fmaf(beta, x1, c[20])))))));
    o2 = fmaf(c[12], p0, fmaf(c[13], p1, fmaf(c[14], p2, fmaf(c[15], p3, fmaf(c[16], p4, fmaf(c[17], p5, fmaf(beta, x2, c[21])))))));
}

__global__ void __launch_bounds__(256, 6)
fused_kernel(const float* __restrict__ t_p,
             const float* __restrict__ xin,
             const float* __restrict__ R,
             const float* __restrict__ m,
             const float* __restrict__ Wl1, const float* __restrict__ Wd1,
             const float* __restrict__ Wl2, const float* __restrict__ Wd2,
             const float* __restrict__ Wl3, const float* __restrict__ Wd3,
             const float* __restrict__ Wl4, const float* __restrict__ Wd4,
             const float* __restrict__ Wb1_lin,
             const float* __restrict__ Wb1_d1, const float* __restrict__ Wb1_d2,
             const float* __restrict__ Wb2_lin,
             const float* __restrict__ Wb2_d1, const float* __restrict__ Wb2_d2,
             const float* __restrict__ Wout,
             float* __restrict__ out, int B)
{
    const int F = 20;
    __shared__ float mm_s[20][3];
    __shared__ float M_s[4][3][3];
    __shared__ float c_s[24];

    int tid = threadIdx.x;
    int i   = blockIdx.x * blockDim.x + tid;
    int n4  = B >> 2;

    // ---- Pre-issue the streaming loads (independent of setup) ----
    float4 va, vb, vd;
    bool active = (i < n4);
    if (active) {
        const float4* p = (const float4*)xin + 3 * (size_t)i;
        va = p[0]; vb = p[1]; vd = p[2];
    }

    // ---- Per-block setup on warp 0 (spill-tolerant path) ----
    if (tid < 32) {
        int lane = tid;

        // Phase A: mm[f][k] = sum_j R[k][j] * m[j][f]
        if (lane < F) {
            float m0 = m[0 * F + lane], m1 = m[1 * F + lane], m2 = m[2 * F + lane];
#pragma unroll
            for (int k = 0; k < 3; k++)
                mm_s[lane][k] = fmaf(R[k * 3 + 0], m0, fmaf(R[k * 3 + 1], m1, R[k * 3 + 2] * m2));
        }

        // Phase B: channel-collapse scalars (warp reduce)
        float a1 = 0.f, b1 = 0.f, a2 = 0.f, b2 = 0.f;
        if (lane < F) {
            float s11 = 0.f, s12 = 0.f, s21 = 0.f, s22 = 0.f;
#pragma unroll 5
            for (int g = 0; g < F; g++) {
                float l1 = Wb1_lin[g], l2 = Wb2_lin[g];
                s11 = fmaf(Wb1_d1[lane * F + g], l1, s11);
                s12 = fmaf(Wb1_d2[lane * F + g], l1, s12);
                s21 = fmaf(Wb2_d1[lane * F + g], l2, s21);
                s22 = fmaf(Wb2_d2[lane * F + g], l2, s22);
            }
            float wo = Wout[lane];
            a1 = wo * s11 * s12;
            b1 = wo * Wb1_lin[lane];
            a2 = wo * s21 * s22;
            b2 = wo * Wb2_lin[lane];
        }
#pragma unroll
        for (int off = 16; off > 0; off >>= 1) {
            a1 += __shfl_down_sync(0xffffffffu, a1, off);
            b1 += __shfl_down_sync(0xffffffffu, b1, off);
            a2 += __shfl_down_sync(0xffffffffu, a2, off);
            b2 += __shfl_down_sync(0xffffffffu, b2, off);
        }
        __syncwarp();

        // Phase C: map_m chains -> M[i] = o^T o  (4 lanes)
        if (lane < 4) {
            const float* Wl = (lane == 0) ? Wl1 : (lane == 1) ? Wl2 : (lane == 2) ? Wl3 : Wl4;
            const float* Wd = (lane == 0) ? Wd1 : (lane == 1) ? Wd2 : (lane == 2) ? Wd3 : Wd4;
            float y0[3][3], d[3][3], o[3][3];
#pragma unroll
            for (int a = 0; a < 3; a++)
#pragma unroll
                for (int k = 0; k < 3; k++) {
                    float s = 0.f;
                    for (int f = 0; f < F; f++) s = fmaf(Wl[a * F + f], mm_s[f][k], s);
                    y0[a][k] = s;
                }
#pragma unroll
            for (int p = 0; p < 3; p++)
#pragma unroll
                for (int k = 0; k < 3; k++)
                    d[p][k] = fmaf(Wd[p * 3 + 0], y0[0][k],
                              fmaf(Wd[p * 3 + 1], y0[1][k], Wd[p * 3 + 2] * y0[2][k]));
#pragma unroll
            for (int f = 0; f < 3; f++) {
                float xd = 0.f, dd = 0.f;
#pragma unroll
                for (int k = 0; k < 3; k++) { xd = fmaf(y0[f][k], d[f][k], xd); dd = fmaf(d[f][k], d[f][k], dd); }
                float kf_xd = -2.f * xd;
                float kf_dd = -2.f * dd;
                float denom = fminf(kf_dd, -1e-12f);
                float coef  = (kf_xd < 0.f) ? 0.f : (kf_xd / denom);
#pragma unroll
                for (int k = 0; k < 3; k++) o[f][k] = fmaf(-coef, d[f][k], y0[f][k]);
            }
#pragma unroll
            for (int k = 0; k < 3; k++)
#pragma unroll
                for (int k2 = 0; k2 < 3; k2++)
                    M_s[lane][k][k2] = fmaf(o[0][k], o[0][k2],
                                       fmaf(o[1][k], o[1][k2], o[2][k] * o[2][k2]));
        }
        __syncwarp();

        // Phase D: assemble the 22 constants (lane 0)
        if (lane == 0) {
            float t  = t_p[0];
            float st = sinf(t), ct = cosf(t);
            float base[3] = {10.f * st, 10.f * ct, 10.f * st};
            float u[3];
#pragma unroll
            for (int k = 0; k < 3; k++)
                u[k] = fmaf(R[k * 3 + 0], base[0], fmaf(R[k * 3 + 1], base[1], R[k * 3 + 2] * base[2]));

            float y3[3], y4[3];
#pragma unroll
            for (int k = 0; k < 3; k++) {
                y3[k] = fmaf(M_s[2][k][0], u[0], fmaf(M_s[2][k][1], u[1], M_s[2][k][2] * u[2]));
                y4[k] = fmaf(M_s[3][k][0], u[0], fmaf(M_s[3][k][1], u[1], M_s[3][k][2] * u[2]));
            }
            float cru0 = y3[1] * y4[2] - y3[2] * y4[1];
            float cru1 = y3[2] * y4[0] - y3[0] * y4[2];
            float cru2 = y3[0] * y4[1] - y3[1] * y4[0];

            c_s[18] = b1;
            c_s[19] = fmaf(a2, cru0, b2 * u[0]);
            c_s[20] = fmaf(a2, cru1, b2 * u[1]);
            c_s[21] = fmaf(a2, cru2, b2 * u[2]);
            c_s[22] = 0.f; c_s[23] = 0.f;

#pragma unroll
            for (int k = 0; k < 3; k++) {
                int k1 = (k + 1) % 3, k2 = (k + 2) % 3;
                float Q[3][3];
#pragma unroll
                for (int ii = 0; ii < 3; ii++)
#pragma unroll
                    for (int jj = 0; jj < 3; jj++)
                        Q[ii][jj] = a1 * (M_s[0][k1][ii] * M_s[1][k2][jj]
                                          - M_s[0][k2][ii] * M_s[1][k1][jj]);
                c_s[k * 6 + 0] = Q[0][0];
                c_s[k * 6 + 1] = Q[1][1];
                c_s[k * 6 + 2] = Q[2][2];
                c_s[k * 6 + 3] = Q[0][1] + Q[1][0];
                c_s[k * 6 + 4] = Q[0][2] + Q[2][0];
                c_s[k * 6 + 5] = Q[1][2] + Q[2][1];
            }
        }
    }
    __syncthreads();

    const float* c = c_s;

    if (active) {
        float r0, r1, r2, r3, r4, r5, r6, r7, r8, r9, r10, r11;
        eval3(c, va.x, va.y, va.z, r0,  r1,  r2);
        eval3(c, va.w, vb.x, vb.y, r3,  r4,  r5);
        eval3(c, vb.z, vb.w, vd.x, r6,  r7,  r8);
        eval3(c, vd.y, vd.z, vd.w, r9,  r10, r11);

        float4* q = (float4*)out + 3 * (size_t)i;
        q[0] = make_float4(r0, r1, r2,  r3);
        q[1] = make_float4(r4, r5, r6,  r7);
        q[2] = make_float4(r8, r9, r10, r11);
    }

    // tail (B not divisible by 4)
    if (i == n4) {
        for (int e = 4 * n4; e < B; e++) {
            float o0, o1, o2;
            eval3(c, xin[3 * e + 0], xin[3 * e + 1], xin[3 * e + 2], o0, o1, o2);
            out[3 * e + 0] = o0;
            out[3 * e + 1] = o1;
            out[3 * e + 2] = o2;
        }
    }
}

extern "C" void kernel_launch(void* const* d_in, const int* in_sizes, int n_in,
                              void* d_out, int out_size)
{
    const float* t_p     = (const float*)d_in[0];
    const float* x       = (const float*)d_in[1];
    const float* R       = (const float*)d_in[2];
    const float* m       = (const float*)d_in[3];
    const float* Wl1     = (const float*)d_in[4];
    const float* Wd1     = (const float*)d_in[5];
    const float* Wl2     = (const float*)d_in[6];
    const float* Wd2     = (const float*)d_in[7];
    const float* Wl3     = (const float*)d_in[8];
    const float* Wd3     = (const float*)d_in[9];
    const float* Wl4     = (const float*)d_in[10];
    const float* Wd4     = (const float*)d_in[11];
    const float* Wb1_lin = (const float*)d_in[12];
    const float* Wb1_d1  = (const float*)d_in[13];
    const float* Wb1_d2  = (const float*)d_in[14];
    const float* Wb2_lin = (const float*)d_in[15];
    const float* Wb2_d1  = (const float*)d_in[16];
    const float* Wb2_d2  = (const float*)d_in[17];
    const float* Wout    = (const float*)d_in[18];

    int B = in_sizes[1] / 3;

    int n4      = B >> 2;
    int threads = n4 + 1;          // +1 thread for the tail
    int block   = 256;
    int grid    = (threads + block - 1) / block;

    fused_kernel<<<grid, block>>>(t_p, x, R, m, Wl1, Wd1, Wl2, Wd2, Wl3, Wd3, Wl4, Wd4,
                                  Wb1_lin, Wb1_d1, Wb1_d2, Wb2_lin, Wb2_d1, Wb2_d2, Wout,
                                  (float*)d_out, B);
}

// round 5
// speedup vs baseline: 1.3135x; 1.3135x over previous
#include <cuda_runtime.h>
#include <math.h>

// out_b[k] = p(x_b) . S[k] + beta * x_b[k] + v0[k]
// p(x) = (x0^2, x1^2, x2^2, x0x1, x0x2, x1x2)
// smem const layout: c[0..17]=S (row k = c[6k..6k+5]), c[18]=beta, c[19..21]=v0

__device__ __forceinline__ void eval3(const float* __restrict__ c,
                                      float x0, float x1, float x2,
                                      float& o0, float& o1, float& o2)
{
    float p0 = x0 * x0, p1 = x1 * x1, p2 = x2 * x2;
    float p3 = x0 * x1, p4 = x0 * x2, p5 = x1 * x2;
    float beta = c[18];
    o0 = fmaf(c[0],  p0, fmaf(c[1],  p1, fmaf(c[2],  p2, fmaf(c[3],  p3, fmaf(c[4],  p4, fmaf(c[5],  p5, fmaf(beta, x0, c[19])))))));
    o1 = fmaf(c[6],  p0, fmaf(c[7],  p1, fmaf(c[8],  p2, fmaf(c[9],  p3, fmaf(c[10], p4, fmaf(c[11], p5, fmaf(beta, x1, c[20])))))));
    o2 = fmaf(c[12], p0, fmaf(c[13], p1, fmaf(c[14], p2, fmaf(c[15], p3, fmaf(c[16], p4, fmaf(c[17], p5, fmaf(beta, x2, c[21])))))));
}

__global__ void __launch_bounds__(256, 6)
fused_kernel(const float* __restrict__ t_p,
             const float* __restrict__ xin,
             const float* __restrict__ R,
             const float* __restrict__ m,
             const float* __restrict__ Wl1, const float* __restrict__ Wd1,
             const float* __restrict__ Wl2, const float* __restrict__ Wd2,
             const float* __restrict__ Wl3, const float* __restrict__ Wd3,
             const float* __restrict__ Wl4, const float* __restrict__ Wd4,
             const float* __restrict__ Wb1_lin,
             const float* __restrict__ Wb1_d1, const float* __restrict__ Wb1_d2,
             const float* __restrict__ Wb2_lin,
             const float* __restrict__ Wb2_d1, const float* __restrict__ Wb2_d2,
             const float* __restrict__ Wout,
             float* __restrict__ out, int B)
{
    const int F = 20;
    __shared__ float s_s[4][20];      // Phase B row dots
    __shared__ float mm_s[20][3];     // Phase A
    __shared__ float y0_s[4][3][3];   // Phase C stage 1
    __shared__ float M_s[4][3][3];
    __shared__ float ab_s[4];         // a1,b1,a2,b2
    __shared__ float c_s[24];

    int tid = threadIdx.x;
    int i   = blockIdx.x * blockDim.x + tid;
    int n4  = B >> 2;

    // ---- Pre-issue the streaming loads (independent of setup) ----
    float4 va, vb, vd;
    bool active = (i < n4);
    if (active) {
        const float4* p = (const float4*)xin + 3 * (size_t)i;
        va = p[0]; vb = p[1]; vd = p[2];
    }

    // ================= Stage 1 (parallel, no deps) =================
    // threads 0..79: s_s[mat][f] = dot(Wmat_row_f, lin)   (20-term, pipelined loads)
    if (tid < 80) {
        int mat = tid / 20, f = tid % 20;
        const float* Wm  = (mat == 0) ? Wb1_d1 : (mat == 1) ? Wb1_d2 : (mat == 2) ? Wb2_d1 : Wb2_d2;
        const float* lin = (mat < 2) ? Wb1_lin : Wb2_lin;
        float s = 0.f;
#pragma unroll
        for (int g = 0; g < 20; g++) s = fmaf(Wm[f * F + g], lin[g], s);
        s_s[mat][f] = s;
    }
    // threads 80..99: mm_s[f][k] = sum_j R[k][j]*m[j][f]
    else if (tid < 100) {
        int f = tid - 80;
        float m0 = m[0 * F + f], m1 = m[1 * F + f], m2 = m[2 * F + f];
#pragma unroll
        for (int k = 0; k < 3; k++)
            mm_s[f][k] = fmaf(R[k * 3 + 0], m0, fmaf(R[k * 3 + 1], m1, R[k * 3 + 2] * m2));
    }
    __syncthreads();

    // ================= Stage 2 =================
    // threads 0..35: y0_s[i][a][k] = sum_f Wl_i[a*F+f] * mm_s[f][k]
    if (tid < 36) {
        int ch = tid / 9, rem = tid % 9, a = rem / 3, k = rem % 3;
        const float* Wl = (ch == 0) ? Wl1 : (ch == 1) ? Wl2 : (ch == 2) ? Wl3 : Wl4;
        float s = 0.f;
#pragma unroll
        for (int f = 0; f < 20; f++) s = fmaf(Wl[a * F + f], mm_s[f][k], s);
        y0_s[ch][a][k] = s;
    }
    // warp 6 (threads 192..223), lanes 0..19: alpha/beta reduction
    if (tid >= 192 && tid < 224) {
        int lane = tid - 192;
        float a1 = 0.f, b1 = 0.f, a2 = 0.f, b2 = 0.f;
        if (lane < F) {
            float wo = Wout[lane];
            a1 = wo * s_s[0][lane] * s_s[1][lane];
            b1 = wo * Wb1_lin[lane];
            a2 = wo * s_s[2][lane] * s_s[3][lane];
            b2 = wo * Wb2_lin[lane];
        }
#pragma unroll
        for (int off = 16; off > 0; off >>= 1) {
            a1 += __shfl_down_sync(0xffffffffu, a1, off);
            b1 += __shfl_down_sync(0xffffffffu, b1, off);
            a2 += __shfl_down_sync(0xffffffffu, a2, off);
            b2 += __shfl_down_sync(0xffffffffu, b2, off);
        }
        if (lane == 0) { ab_s[0] = a1; ab_s[1] = b1; ab_s[2] = a2; ab_s[3] = b2; }
    }
    __syncthreads();

    // ================= Stage 3: small 3x3 tail (4 threads) =================
    if (tid < 4) {
        const float* Wd = (tid == 0) ? Wd1 : (tid == 1) ? Wd2 : (tid == 2) ? Wd3 : Wd4;
        float d[3][3], o[3][3];
#pragma unroll
        for (int p = 0; p < 3; p++)
#pragma unroll
            for (int k = 0; k < 3; k++)
                d[p][k] = fmaf(Wd[p * 3 + 0], y0_s[tid][0][k],
                          fmaf(Wd[p * 3 + 1], y0_s[tid][1][k], Wd[p * 3 + 2] * y0_s[tid][2][k]));
#pragma unroll
        for (int f = 0; f < 3; f++) {
            float xd = 0.f, dd = 0.f;
#pragma unroll
            for (int k = 0; k < 3; k++) {
                xd = fmaf(y0_s[tid][f][k], d[f][k], xd);
                dd = fmaf(d[f][k], d[f][k], dd);
            }
            float kf_xd = -2.f * xd;
            float kf_dd = -2.f * dd;
            float denom = fminf(kf_dd, -1e-12f);
            float coef  = (kf_xd < 0.f) ? 0.f : (kf_xd / denom);
#pragma unroll
            for (int k = 0; k < 3; k++) o[f][k] = fmaf(-coef, d[f][k], y0_s[tid][f][k]);
        }
#pragma unroll
        for (int k = 0; k < 3; k++)
#pragma unroll
            for (int k2 = 0; k2 < 3; k2++)
                M_s[tid][k][k2] = fmaf(o[0][k], o[0][k2],
                                  fmaf(o[1][k], o[1][k2], o[2][k] * o[2][k2]));
    }
    __syncthreads();

    // ================= Stage 4: assemble constants (thread 0) =================
    if (tid == 0) {
        float a1 = ab_s[0], b1 = ab_s[1], a2 = ab_s[2], b2 = ab_s[3];
        float t  = t_p[0];
        float st = sinf(t), ct = cosf(t);
        float base[3] = {10.f * st, 10.f * ct, 10.f * st};
        float u[3];
#pragma unroll
        for (int k = 0; k < 3; k++)
            u[k] = fmaf(R[k * 3 + 0], base[0], fmaf(R[k * 3 + 1], base[1], R[k * 3 + 2] * base[2]));

        float y3[3], y4[3];
#pragma unroll
        for (int k = 0; k < 3; k++) {
            y3[k] = fmaf(M_s[2][k][0], u[0], fmaf(M_s[2][k][1], u[1], M_s[2][k][2] * u[2]));
            y4[k] = fmaf(M_s[3][k][0], u[0], fmaf(M_s[3][k][1], u[1], M_s[3][k][2] * u[2]));
        }
        float cru0 = y3[1] * y4[2] - y3[2] * y4[1];
        float cru1 = y3[2] * y4[0] - y3[0] * y4[2];
        float cru2 = y3[0] * y4[1] - y3[1] * y4[0];

        c_s[18] = b1;
        c_s[19] = fmaf(a2, cru0, b2 * u[0]);
        c_s[20] = fmaf(a2, cru1, b2 * u[1]);
        c_s[21] = fmaf(a2, cru2, b2 * u[2]);
        c_s[22] = 0.f; c_s[23] = 0.f;

#pragma unroll
        for (int k = 0; k < 3; k++) {
            int k1 = (k + 1) % 3, k2 = (k + 2) % 3;
            float Q[3][3];
#pragma unroll
            for (int ii = 0; ii < 3; ii++)
#pragma unroll
                for (int jj = 0; jj < 3; jj++)
                    Q[ii][jj] = a1 * (M_s[0][k1][ii] * M_s[1][k2][jj]
                                      - M_s[0][k2][ii] * M_s[1][k1][jj]);
            c_s[k * 6 + 0] = Q[0][0];
            c_s[k * 6 + 1] = Q[1][1];
            c_s[k * 6 + 2] = Q[2][2];
            c_s[k * 6 + 3] = Q[0][1] + Q[1][0];
            c_s[k * 6 + 4] = Q[0][2] + Q[2][0];
            c_s[k * 6 + 5] = Q[1][2] + Q[2][1];
        }
    }
    __syncthreads();

    const float* c = c_s;

    if (active) {
        float r0, r1, r2, r3, r4, r5, r6, r7, r8, r9, r10, r11;
        eval3(c, va.x, va.y, va.z, r0,  r1,  r2);
        eval3(c, va.w, vb.x, vb.y, r3,  r4,  r5);
        eval3(c, vb.z, vb.w, vd.x, r6,  r7,  r8);
        eval3(c, vd.y, vd.z, vd.w, r9,  r10, r11);

        float4* q = (float4*)out + 3 * (size_t)i;
        q[0] = make_float4(r0, r1, r2,  r3);
        q[1] = make_float4(r4, r5, r6,  r7);
        q[2] = make_float4(r8, r9, r10, r11);
    }

    // tail (B not divisible by 4)
    if (i == n4) {
        for (int e = 4 * n4; e < B; e++) {
            float o0, o1, o2;
            eval3(c, xin[3 * e + 0], xin[3 * e + 1], xin[3 * e + 2], o0, o1, o2);
            out[3 * e + 0] = o0;
            out[3 * e + 1] = o1;
            out[3 * e + 2] = o2;
        }
    }
}

extern "C" void kernel_launch(void* const* d_in, const int* in_sizes, int n_in,
                              void* d_out, int out_size)
{
    const float* t_p     = (const float*)d_in[0];
    const float* x       = (const float*)d_in[1];
    const float* R       = (const float*)d_in[2];
    const float* m       = (const float*)d_in[3];
    const float* Wl1     = (const float*)d_in[4];
    const float* Wd1     = (const float*)d_in[5];
    const float* Wl2     = (const float*)d_in[6];
    const float* Wd2     = (const float*)d_in[7];
    const float* Wl3     = (const float*)d_in[8];
    const float* Wd3     = (const float*)d_in[9];
    const float* Wl4     = (const float*)d_in[10];
    const float* Wd4     = (const float*)d_in[11];
    const float* Wb1_lin = (const float*)d_in[12];
    const float* Wb1_d1  = (const float*)d_in[13];
    const float* Wb1_d2  = (const float*)d_in[14];
    const float* Wb2_lin = (const float*)d_in[15];
    const float* Wb2_d1  = (const float*)d_in[16];
    const float* Wb2_d2  = (const float*)d_in[17];
    const float* Wout    = (const float*)d_in[18];

    int B = in_sizes[1] / 3;

    int n4      = B >> 2;
    int threads = n4 + 1;          // +1 thread for the tail
    int block   = 256;
    int grid    = (threads + block - 1) / block;

    fused_kernel<<<grid, block>>>(t_p, x, R, m, Wl1, Wd1, Wl2, Wd2, Wl3, Wd3, Wl4, Wd4,
                                  Wb1_lin, Wb1_d1, Wb1_d2, Wb2_lin, Wb2_d1, Wb2_d2, Wout,
                                  (float*)d_out, B);
}